// round 3
// baseline (speedup 1.0000x reference)
#include <cuda_runtime.h>
#include <math.h>

constexpr int NB = 128, NA = 2, NH = 128, NW = 128;
constexpr int PLANE = NH * NW;
constexpr float THRESH = 0.6f;
constexpr float OBJ_SCALE = 5.0f;
constexpr float LN_MARGIN = 0.55961579f;   // ln(1.75) > ln(5/3) safety margin
constexpr int NBLOCKS = 2048;              // 524288 threads * 8 cells = 4.19M cells

// Persistent accumulators (zero-initialized at module load; reset by last block)
__device__ double g_conf2 = 0.0;
__device__ unsigned long long g_cnt = 0ull;
__device__ float  g_sel = 0.0f;
__device__ unsigned g_done = 0u;

__device__ __forceinline__ float sig_precise(float x) { return 1.0f / (1.0f + expf(-x)); }
__device__ __forceinline__ float sig_fast(float x) {
    return __fdividef(1.0f, 1.0f + __expf(-x));
}

__global__ void __launch_bounds__(256) k_fused(const float* __restrict__ out,
                                               const float* __restrict__ tgt,
                                               const float* __restrict__ anc,
                                               float* __restrict__ res) {
    int tid = blockIdx.x * 256 + threadIdx.x;
    int i8 = (tid & 15) * 8;          // 8 consecutive columns
    int r  = tid >> 4;
    int j  = r & 127; r >>= 7;        // row
    int a  = r & 1;                   // anchor   (constant per block)
    int b  = r >> 1;                  // batch    (constant per block)

    // ---- per-batch constants, computed once per block ----
    __shared__ float s_gx, s_gy, s_gw, s_gh;       // gt box (grid units)
    __shared__ float s_lo, s_hi;                   // screen bounds on w+h (this a)
    __shared__ float s_tx, s_ty, s_tw, s_th, s_scl;
    __shared__ float s_aw, s_ah;                   // this anchor
    __shared__ int   s_excl;
    if (threadIdx.x == 0) {
        float t0 = tgt[b*4+0], t1 = tgt[b*4+1], t2 = tgt[b*4+2], t3 = tgt[b*4+3];
        float gx = t0 * (float)NW, gy = t1 * (float)NH;
        float gw = t2 * (float)NW, gh = t3 * (float)NH;
        float a0w = anc[0], a0h = anc[1], a1w = anc[2], a1h = anc[3];

        float ga = gw * gh;
        float i0 = fminf(gw, a0w) * fminf(gh, a0h);
        float u0 = ga + 1e-16f + a0w * a0h - i0;
        float i1 = fminf(gw, a1w) * fminf(gh, a1h);
        float u1 = ga + 1e-16f + a1w * a1h - i1;
        int best = (i1 / u1) > (i0 / u0) ? 1 : 0;

        s_gx = gx; s_gy = gy; s_gw = gw; s_gh = gh;
        s_excl = best * PLANE + (int)gy * NW + (int)gx;

        float aw = a ? a1w : a0w;
        float ah = a ? a1h : a0h;
        s_aw = aw; s_ah = ah;
        float c = logf(ga / (aw * ah));
        s_lo = c - LN_MARGIN; s_hi = c + LN_MARGIN;

        float bw = best ? a1w : a0w;
        float bh = best ? a1h : a0h;
        s_tx = gx - floorf(gx); s_ty = gy - floorf(gy);
        s_tw = logf(gw / bw + 1e-16f); s_th = logf(gh / bh + 1e-16f);
        s_scl = 2.0f - t2 * t3;
    }
    __syncthreads();

    // ---- streaming loads: w, h, conf (always) ----
    size_t base = ((size_t)(b * 10 + a * 5) * NH + j) * NW + i8;
    float4 w0 = *(const float4*)(out + base + 2 * (size_t)PLANE);
    float4 w1 = *(const float4*)(out + base + 2 * (size_t)PLANE + 4);
    float4 h0 = *(const float4*)(out + base + 3 * (size_t)PLANE);
    float4 h1 = *(const float4*)(out + base + 3 * (size_t)PLANE + 4);
    float4 c0 = *(const float4*)(out + base + 4 * (size_t)PLANE);
    float4 c1 = *(const float4*)(out + base + 4 * (size_t)PLANE + 4);

    float pw8[8] = {w0.x,w0.y,w0.z,w0.w,w1.x,w1.y,w1.z,w1.w};
    float ph8[8] = {h0.x,h0.y,h0.z,h0.w,h1.x,h1.y,h1.z,h1.w};
    float pc8[8] = {c0.x,c0.y,c0.z,c0.w,c1.x,c1.y,c1.z,c1.w};

    float lo = s_lo, hi = s_hi;
    int   excl = s_excl;
    int   lbase = a * PLANE + j * NW + i8;

    bool pass[4*2];
    bool anyp = false;
    #pragma unroll
    for (int k = 0; k < 8; k++) {
        float s = pw8[k] + ph8[k];
        pass[k] = (s > lo) && (s < hi);
        anyp |= pass[k];
    }
    bool own_excl = (excl >= lbase) && (excl < lbase + 8);
    bool noobj[8] = {true,true,true,true,true,true,true,true};
    float selv = 0.0f;

    if (anyp | own_excl) {
        float4 x0 = *(const float4*)(out + base);
        float4 x1 = *(const float4*)(out + base + 4);
        float4 y0 = *(const float4*)(out + base + (size_t)PLANE);
        float4 y1 = *(const float4*)(out + base + (size_t)PLANE + 4);
        float px8[8] = {x0.x,x0.y,x0.z,x0.w,x1.x,x1.y,x1.z,x1.w};
        float py8[8] = {y0.x,y0.y,y0.z,y0.w,y1.x,y1.y,y1.z,y1.w};

        float gxm = s_gx - s_gw * 0.5f, gxM = s_gx + s_gw * 0.5f;
        float gym = s_gy - s_gh * 0.5f, gyM = s_gy + s_gh * 0.5f;
        float garea = s_gw * s_gh;
        float aw = s_aw, ah = s_ah;

        #pragma unroll
        for (int k = 0; k < 8; k++) {
            if (pass[k]) {
                float px = sig_fast(px8[k]) + (float)(i8 + k);
                float py = sig_fast(py8[k]) + (float)j;
                float pw = __expf(pw8[k]) * aw;
                float ph = __expf(ph8[k]) * ah;
                float mx = fminf(px - pw * 0.5f, gxm);
                float Mx = fmaxf(px + pw * 0.5f, gxM);
                float my = fminf(py - ph * 0.5f, gym);
                float My = fmaxf(py + ph * 0.5f, gyM);
                float cw = pw + s_gw - (Mx - mx);
                float ch = ph + s_gh - (My - my);
                float carea = cw * ch;
                float uarea = pw * ph + garea - carea;
                noobj[k] = (cw <= 0.0f) || (ch <= 0.0f) || (carea <= THRESH * uarea);
            }
        }
        if (own_excl) {
            int k = excl - lbase;
            noobj[k] = false;
            float xs = sig_precise(px8[k]);
            float ys = sig_precise(py8[k]);
            float cs = sig_precise(pc8[k]);
            float sc = s_scl;
            float dx = (xs - s_tx) * sc, dy = (ys - s_ty) * sc;
            float dw = (pw8[k] - s_tw) * sc, dh = (ph8[k] - s_th) * sc;
            selv = (dx*dx + dy*dy + dw*dw + dh*dh
                 + OBJ_SCALE * (cs - 1.0f) * (cs - 1.0f)) * (1.0f / (float)NB);
        }
    }

    float conf2f = 0.0f;
    int cnt = 0;
    #pragma unroll
    for (int k = 0; k < 8; k++) {
        if (noobj[k]) {
            float rr = sig_fast(pc8[k]);
            conf2f += rr * rr;
            cnt++;
        }
    }

    // ---- block reduce (conf2, cnt, selv) ----
    #pragma unroll
    for (int o = 16; o > 0; o >>= 1) {
        conf2f += __shfl_down_sync(0xffffffffu, conf2f, o);
        cnt    += __shfl_down_sync(0xffffffffu, cnt, o);
        selv   += __shfl_down_sync(0xffffffffu, selv, o);
    }
    __shared__ double sh_c2[8];
    __shared__ int    sh_ct[8];
    __shared__ float  sh_sv[8];
    int lane = threadIdx.x & 31, wrp = threadIdx.x >> 5;
    if (lane == 0) { sh_c2[wrp] = (double)conf2f; sh_ct[wrp] = cnt; sh_sv[wrp] = selv; }
    __syncthreads();
    if (wrp == 0) {
        double c2 = (lane < 8) ? sh_c2[lane] : 0.0;
        int    ct = (lane < 8) ? sh_ct[lane] : 0;
        float  sv = (lane < 8) ? sh_sv[lane] : 0.0f;
        #pragma unroll
        for (int o = 4; o > 0; o >>= 1) {
            c2 += __shfl_down_sync(0xffffffffu, c2, o);
            ct += __shfl_down_sync(0xffffffffu, ct, o);
            sv += __shfl_down_sync(0xffffffffu, sv, o);
        }
        if (lane == 0) {
            atomicAdd(&g_conf2, c2);
            atomicAdd(&g_cnt, (unsigned long long)ct);
            if (sv != 0.0f) atomicAdd(&g_sel, sv);
            __threadfence();
            unsigned old = atomicAdd(&g_done, 1u);
            if (old == (unsigned)(NBLOCKS - 1)) {
                // last block: all prior atomics are visible (fence + counter order)
                __threadfence();
                res[0] = g_sel + (float)(g_conf2 / (double)g_cnt);
                // reset for next graph replay
                g_conf2 = 0.0; g_cnt = 0ull; g_sel = 0.0f; g_done = 0u;
            }
        }
    }
}

extern "C" void kernel_launch(void* const* d_in, const int* in_sizes, int n_in,
                              void* d_out, int out_size) {
    const float* out = (const float*)d_in[0];   // (128, 10, 128, 128)
    const float* tgt = (const float*)d_in[1];   // (128, 4)
    const float* anc = (const float*)d_in[2];   // (2, 2)
    float* res = (float*)d_out;

    k_fused<<<NBLOCKS, 256>>>(out, tgt, anc, res);
}